// round 5
// baseline (speedup 1.0000x reference)
#include <cuda_runtime.h>
#include <cuda_bf16.h>
#include <cstdint>

// Problem constants (fixed by the dataset)
#define BB  16
#define TT  128   // txt_T
#define MM  512   // mel_T
#define NC  80    // N_MEL

// k_logprob tiling: block tile 32t x 128m, 128 threads, per-thread 4t x 8m
#define TBLK 32
#define MBLK 128
#define K1_THREADS 128

// Scratch (no cudaMalloc allowed).
__device__ __align__(16) float g_elp[(size_t)BB * MM * TT + 4096]; // exp(lp), [b][m][t]
__device__ float g_alpha[BB];
__device__ unsigned g_cnt = 0;

// smem layout (bytes)
#define SM_X2_OFF 0
#define SM_X_OFF  (NC * 64 * 8)                 // 40960
#define SM_WA_OFF (SM_X_OFF + NC * 64 * 8)      // 81920
#define SM_KP_OFF (SM_WA_OFF + TBLK * NC * 8)   // 102400
#define SM_KC_OFF (SM_KP_OFF + TBLK * 4 * 4)    // 102912
#define SM_TOTAL  (SM_KC_OFF + TBLK * 4)        // 103040

// ---- packed f32x2 helpers (sm_103a dual-fp32 pipe; PTX-only) ----
__device__ __forceinline__ void fma2(unsigned long long& d,
                                     unsigned long long a,
                                     unsigned long long b) {
    asm("fma.rn.f32x2 %0, %1, %2, %0;" : "+l"(d) : "l"(a), "l"(b));
}
__device__ __forceinline__ unsigned long long pack2(float lo, float hi) {
    unsigned long long r;
    asm("mov.b64 %0, {%1, %2};" : "=l"(r) : "f"(lo), "f"(hi));
    return r;
}
__device__ __forceinline__ float2 unpack2(unsigned long long v) {
    float lo, hi;
    asm("mov.b64 {%0, %1}, %2;" : "=f"(lo), "=f"(hi) : "l"(v));
    return make_float2(lo, hi);
}

// ---------------------------------------------------------------------------
// Kernel 1: log_prob_matrix + exp(log_prob) scratch.  (unchanged, proven)
// ---------------------------------------------------------------------------
__global__ __launch_bounds__(K1_THREADS)
void k_logprob(const float* __restrict__ ml,     // [B, TT, 2*NC]
               const float* __restrict__ mel,    // [B, NC, MM]
               float* __restrict__ lpm)          // [B, TT, MM] (d_out + 1)
{
    extern __shared__ char sm[];
    unsigned long long* X2s = (unsigned long long*)(sm + SM_X2_OFF); // [NC][64]
    unsigned long long* Xs  = (unsigned long long*)(sm + SM_X_OFF);  // [NC][64]
    float2* wa = (float2*)(sm + SM_WA_OFF);  // [TBLK][NC] = {w, a}
    float*  kp = (float*) (sm + SM_KP_OFF);  // [TBLK][4]
    float*  kc = (float*) (sm + SM_KC_OFF);  // [TBLK]

    const int b   = blockIdx.z;
    const int t0  = blockIdx.y * TBLK;
    const int m0  = blockIdx.x * MBLK;
    const int tid = threadIdx.x;

    // Phase A: per-t coefficients. thread -> (t = tid/4, c-lane = tid%4)
    {
        const int t  = tid >> 2;
        const int cl = tid & 3;
        const float* row = ml + ((size_t)(b * TT + t0 + t)) * (2 * NC);
        float kpart = 0.f;
#pragma unroll
        for (int i = 0; i < 20; i++) {
            int c = cl + 4 * i;
            float mu = row[c];
            float lv = row[NC + c];
            float w  = __expf(-lv);
            float a  = -2.f * w * mu;
            wa[t * NC + c] = make_float2(w, a);
            kpart += __fmaf_rn(w * mu, mu, lv);
        }
        kp[t * 4 + cl] = kpart;
    }

    // Phase B: melspec tile -> packed (x2 pair) and (x pair)
    for (int lin = tid; lin < NC * 64; lin += K1_THREADS) {
        int c = lin >> 6;
        int p = lin & 63;
        float2 x = ((const float2*)(mel + ((size_t)(b * NC + c)) * MM + m0))[p];
        X2s[c * 64 + p] = pack2(x.x * x.x, x.y * x.y);
        Xs [c * 64 + p] = pack2(x.x, x.y);
    }
    __syncthreads();

    if (tid < TBLK) {
        kc[tid] = kp[tid*4] + kp[tid*4+1] + kp[tid*4+2] + kp[tid*4+3];
    }
    __syncthreads();

    // Phase C: FFMA2 micro-tile 4t x 4 m-pairs
    const int tx = tid & 15;     // m-pair lane
    const int ty = tid >> 4;     // t group (4 consecutive t)
    unsigned long long acc[4][4];
#pragma unroll
    for (int tt = 0; tt < 4; tt++)
#pragma unroll
        for (int j = 0; j < 4; j++) acc[tt][j] = 0ull;

#pragma unroll 2
    for (int c = 0; c < NC; c++) {
        unsigned long long x2p[4], xp[4];
#pragma unroll
        for (int j = 0; j < 4; j++) {
            x2p[j] = X2s[c * 64 + tx + 16 * j];
            xp[j]  = Xs [c * 64 + tx + 16 * j];
        }
#pragma unroll
        for (int tt = 0; tt < 4; tt++) {
            float2 wv = wa[(4 * ty + tt) * NC + c];
            unsigned long long ww = pack2(wv.x, wv.x);
            unsigned long long aa = pack2(wv.y, wv.y);
#pragma unroll
            for (int j = 0; j < 4; j++) {
                fma2(acc[tt][j], ww, x2p[j]);
                fma2(acc[tt][j], aa, xp[j]);
            }
        }
    }

    // Epilogue
    const float inv = -1.f / (2.f * NC);
    float kt[4];
#pragma unroll
    for (int tt = 0; tt < 4; tt++) kt[tt] = kc[4 * ty + tt];
    const int tg = t0 + 4 * ty;

#pragma unroll
    for (int j = 0; j < 4; j++) {
        const int me = m0 + 2 * (tx + 16 * j);   // even m
        float e0[4], e1[4];
#pragma unroll
        for (int tt = 0; tt < 4; tt++) {
            float2 v = unpack2(acc[tt][j]);
            float lp0 = (v.x + kt[tt]) * inv;
            float lp1 = (v.y + kt[tt]) * inv;
            float* dst = lpm + ((size_t)(b * TT + tg + tt)) * MM + me;
            dst[0] = lp0;          // d_out+1 is only 4B aligned: scalar stores
            dst[1] = lp1;
            e0[tt] = __expf(lp0);
            e1[tt] = __expf(lp1);
        }
        *(float4*)(g_elp + ((size_t)b * MM + me)     * TT + tg) =
            make_float4(e0[0], e0[1], e0[2], e0[3]);
        *(float4*)(g_elp + ((size_t)b * MM + me + 1) * TT + tg) =
            make_float4(e1[0], e1[1], e1[2], e1[3]);
    }
}

// ---------------------------------------------------------------------------
// Kernel 2: probability-domain forward scan, one warp per batch.
// CHANGE vs proven round-4 scan: 2-step fusion. One pair of INDEPENDENT
// shuffles per 2 m-steps instead of one serially-dependent shuffle per step:
//   v[j] = A[j]*(q[j]+q[j-1]) + B[j]*(q[j-1]+q[j-2])
//   A[j] = ea[j]*eb[j], B[j] = eb[j]*ea[j-1]   (ea=E[m], eb=E[m+1])
// ea[j-1] at the lane boundary comes from a scalar load (off the q-chain).
// Rescale every 16 m-steps (proven cadence). Tail: proven single-step freeze.
// ---------------------------------------------------------------------------
__device__ __forceinline__ void scan_rescale(float& q0, float& q1, float& q2,
                                             float& q3, int& kTot) {
    float s = fmaxf(fmaxf(q0, q1), fmaxf(q2, q3));
#pragma unroll
    for (int o = 16; o; o >>= 1)
        s = fmaxf(s, __shfl_xor_sync(0xffffffffu, s, o));
    if (s > 0.f) {
        int eb = (__float_as_int(s) >> 23) & 0xff;
        float sc = __int_as_float((254 - eb) << 23);
        q0 *= sc; q1 *= sc; q2 *= sc; q3 *= sc;
        kTot += eb - 127;
    }
}

__global__ __launch_bounds__(32)
void k_scan(const float* __restrict__ out_base,  // d_out (out[0]=loss, +1=lpm)
            const int* __restrict__ tlen,
            const int* __restrict__ mlen)
{
    const int b    = blockIdx.x;
    const int lane = threadIdx.x;
    const float*  Es = g_elp + (size_t)b * MM * TT;      // scalar view [m][t]
    const float4* __restrict__ Ev = (const float4*)Es;   // [m][32 lanes]

    const int mel_len = mlen[b];
    const int txt_len = tlen[b];
    const int last    = mel_len - 1;          // >= 255 for this dataset

    float q0 = (lane == 0) ? 1.f : 0.f;
    float q1 = 0.f, q2 = 0.f, q3 = 0.f;
    const bool isL0 = (lane == 0);
    const float L0 = out_base[1 + (size_t)b * TT * MM];  // lp[b,0,0]
    int kTot = 0;
    const int tb = 4 * lane - 1;              // t-index of boundary neighbor

    // fused double-step: ea=E[m], eb=E[m+1], eam1 = E[m][4*lane-1]
#define DSTEP(ea, eb, eam1)                                         \
    {                                                               \
        float s3 = __shfl_up_sync(0xffffffffu, q3, 1);              \
        float s2 = __shfl_up_sync(0xffffffffu, q2, 1);              \
        if (isL0) { s3 = 0.f; s2 = 0.f; }                           \
        float A0 = (ea).x * (eb).x, A1 = (ea).y * (eb).y;           \
        float A2 = (ea).z * (eb).z, A3 = (ea).w * (eb).w;           \
        float B0 = (eam1) * (eb).x, B1 = (ea).x * (eb).y;           \
        float B2 = (ea).y * (eb).z, B3 = (ea).z * (eb).w;           \
        float n0 = A0 * (q0 + s3) + B0 * (s3 + s2);                 \
        float n1 = A1 * (q1 + q0) + B1 * (q0 + s3);                 \
        float n2 = A2 * (q2 + q1) + B2 * (q1 + q0);                 \
        float n3 = A3 * (q3 + q2) + B3 * (q2 + q1);                 \
        q0 = n0; q1 = n1; q2 = n2; q3 = n3;                         \
    }

    // proven single-step (tail only)
#define STEPQ_PRED(e, act)                                        \
    {                                                             \
        float top = __shfl_up_sync(0xffffffffu, q3, 1);           \
        if (isL0) top = 0.f;                                      \
        float n0 = (q0 + top) * (e).x;                            \
        float n1 = (q1 + q0)  * (e).y;                            \
        float n2 = (q2 + q1)  * (e).z;                            \
        float n3 = (q3 + q2)  * (e).w;                            \
        q0 = (act) ? n0 : q0;                                     \
        q1 = (act) ? n1 : q1;                                     \
        q2 = (act) ? n2 : q2;                                     \
        q3 = (act) ? n3 : q3;                                     \
    }

    // Half-rings: R1 holds m..m+15, R2 holds m+16..m+31 (raw E float4),
    // em1a/em1b hold the boundary scalar E[m+2i][4*lane-1] per double-step.
    float4 R1[16], R2[16];
    float em1a[8], em1b[8];
#pragma unroll
    for (int i = 0; i < 16; i++) R1[i] = Ev[(size_t)(1 + i) * 32 + lane];
#pragma unroll
    for (int i = 0; i < 16; i++) R2[i] = Ev[(size_t)(17 + i) * 32 + lane];
#pragma unroll
    for (int i = 0; i < 8; i++)  em1a[i] = Es[(size_t)(1 + 2 * i) * TT + tb];
#pragma unroll
    for (int i = 0; i < 8; i++)  em1b[i] = Es[(size_t)(17 + 2 * i) * TT + tb];

    int m = 1;
    while (m + 31 <= last) {
        // 8 double-steps over R1 (m .. m+15)
#pragma unroll
        for (int i = 0; i < 8; i++) DSTEP(R1[2 * i], R1[2 * i + 1], em1a[i]);
        // batched refill R1 <- m+32..m+47 (clamped)
#pragma unroll
        for (int i = 0; i < 16; i++) {
            int mi = m + 32 + i; if (mi > MM - 1) mi = MM - 1;
            R1[i] = Ev[(size_t)mi * 32 + lane];
        }
#pragma unroll
        for (int i = 0; i < 8; i++) {
            int mi = m + 32 + 2 * i; if (mi > MM - 1) mi = MM - 1;
            em1a[i] = Es[(size_t)mi * TT + tb];
        }
        scan_rescale(q0, q1, q2, q3, kTot);

        // 8 double-steps over R2 (m+16 .. m+31)
#pragma unroll
        for (int i = 0; i < 8; i++) DSTEP(R2[2 * i], R2[2 * i + 1], em1b[i]);
        // batched refill R2 <- m+48..m+63 (clamped)
#pragma unroll
        for (int i = 0; i < 16; i++) {
            int mi = m + 48 + i; if (mi > MM - 1) mi = MM - 1;
            R2[i] = Ev[(size_t)mi * 32 + lane];
        }
#pragma unroll
        for (int i = 0; i < 8; i++) {
            int mi = m + 48 + 2 * i; if (mi > MM - 1) mi = MM - 1;
            em1b[i] = Es[(size_t)mi * TT + tb];
        }
        scan_rescale(q0, q1, q2, q3, kTot);
        m += 32;
    }

    // tail: <= 31 remaining single steps; rings hold m..m+31
#pragma unroll
    for (int i = 0; i < 16; i++) STEPQ_PRED(R1[i], (m + i)      <= last);
#pragma unroll
    for (int i = 0; i < 16; i++) STEPQ_PRED(R2[i], (m + 16 + i) <= last);

#undef DSTEP
#undef STEPQ_PRED

    // extract alpha_last, fold loss reduction
    {
        const int idx = txt_len - 1;
        const int sel = idx & 3;
        float v = (sel == 0) ? q0 : (sel == 1) ? q1 : (sel == 2) ? q2 : q3;
        v = __shfl_sync(0xffffffffu, v, idx >> 2);
        if (lane == 0) {
            float alpha = __logf(v) + (float)kTot * 0.69314718055994531f + L0;
            g_alpha[b] = alpha / (float)mel_len;
            __threadfence();
            unsigned ticket = atomicAdd(&g_cnt, 1u);
            if (ticket == BB - 1) {
                __threadfence();
                float s = 0.f;
#pragma unroll
                for (int i = 0; i < BB; i++)
                    s += ((volatile float*)g_alpha)[i];
                ((float*)out_base)[0] = -s * (1.f / BB);
                g_cnt = 0;   // reset for next graph replay
            }
        }
    }
}

// ---------------------------------------------------------------------------
extern "C" void kernel_launch(void* const* d_in, const int* in_sizes, int n_in,
                              void* d_out, int out_size)
{
    const float* ml  = (const float*)d_in[0];   // mu_logvar [16,128,160]
    const float* mel = (const float*)d_in[1];   // melspec   [16,80,512]
    const int*   tl  = (const int*)d_in[2];     // text_lengths [16]
    const int*   mll = (const int*)d_in[3];     // mel_lengths  [16]
    float* out = (float*)d_out;                 // [0]=loss, [1..]=log_prob_matrix

    cudaFuncSetAttribute(k_logprob,
                         cudaFuncAttributeMaxDynamicSharedMemorySize, SM_TOTAL);

    k_logprob<<<dim3(MM / MBLK, TT / TBLK, BB), K1_THREADS, SM_TOTAL>>>(
        ml, mel, out + 1);
    k_scan<<<BB, 32>>>(out, tl, mll);
}